// round 5
// baseline (speedup 1.0000x reference)
#include <cuda_runtime.h>

// out[i,j] = x0[i,j] * (x_l[i] . w) + b[j] + x_l[i,j]
// B = 65536 rows, DIM = 1024.
// One block per row, 128 threads, 8 floats (32B) per thread via Blackwell
// 256-bit vector loads/stores (ld/st.global.v8.f32). Halves the LDG/STG
// count vs the float4 version to raise L1tex wavefront efficiency.

#define DIM 1024
#define THREADS 128   // DIM / 8

__device__ __forceinline__ void ldg_v8(const float* p, float r[8]) {
    asm volatile(
        "ld.global.v8.f32 {%0,%1,%2,%3,%4,%5,%6,%7}, [%8];"
        : "=f"(r[0]), "=f"(r[1]), "=f"(r[2]), "=f"(r[3]),
          "=f"(r[4]), "=f"(r[5]), "=f"(r[6]), "=f"(r[7])
        : "l"(p));
}

__device__ __forceinline__ void stg_v8(float* p, const float r[8]) {
    asm volatile(
        "st.global.v8.f32 [%0], {%1,%2,%3,%4,%5,%6,%7,%8};"
        :: "l"(p),
           "f"(r[0]), "f"(r[1]), "f"(r[2]), "f"(r[3]),
           "f"(r[4]), "f"(r[5]), "f"(r[6]), "f"(r[7])
        : "memory");
}

__global__ __launch_bounds__(THREADS) void dcn_kernel(
    const float* __restrict__ x_l,
    const float* __restrict__ x_0,
    const float* __restrict__ w,
    const float* __restrict__ b,
    float* __restrict__ out)
{
    const int row = blockIdx.x;
    const int t   = threadIdx.x;
    const size_t base = (size_t)row * DIM + t * 8;

    // Front-batch both DRAM streams (two 32B loads in flight) + resident w/b.
    float a[8], c[8], wv[8], bv[8];
    ldg_v8(x_l + base, a);
    ldg_v8(x_0 + base, c);
    ldg_v8(w + t * 8, wv);
    ldg_v8(b + t * 8, bv);

    // Partial dot product over this thread's 8 elements.
    float local = 0.0f;
    #pragma unroll
    for (int i = 0; i < 8; i++) local = fmaf(a[i], wv[i], local);

    // Warp butterfly reduce.
    #pragma unroll
    for (int off = 16; off > 0; off >>= 1)
        local += __shfl_xor_sync(0xffffffffu, local, off);

    __shared__ float warpsum[THREADS / 32];
    if ((t & 31) == 0) warpsum[t >> 5] = local;
    __syncthreads();

    float s = 0.0f;
    #pragma unroll
    for (int i = 0; i < THREADS / 32; i++) s += warpsum[i];

    // Pure-register epilogue, one 256-bit store.
    float o[8];
    #pragma unroll
    for (int i = 0; i < 8; i++) o[i] = fmaf(c[i], s, bv[i] + a[i]);
    stg_v8(out + base, o);
}

extern "C" void kernel_launch(void* const* d_in, const int* in_sizes, int n_in,
                              void* d_out, int out_size)
{
    const float* x_l = (const float*)d_in[0];
    const float* x_0 = (const float*)d_in[1];
    const float* w   = (const float*)d_in[2];
    const float* b   = (const float*)d_in[3];
    float* out       = (float*)d_out;

    const int B = in_sizes[0] / DIM;  // 65536
    dcn_kernel<<<B, THREADS>>>(x_l, x_0, w, b, out);
}

// round 6
// speedup vs baseline: 1.0176x; 1.0176x over previous
#include <cuda_runtime.h>

// out[i,j] = x0[i,j] * (x_l[i] . w) + b[j] + x_l[i,j]
// B = 65536 rows, DIM = 1024.
// R4 structure (one block/row, 256 threads, float4, front-batched loads,
// default load cache-ops) + __stcs ONLY on the output store: the 256 MB
// write-once stream is marked evict-first so it doesn't displace the two
// read streams' sectors in the 126 MB L2.

#define DIM 1024
#define THREADS 256  // DIM/4

__global__ __launch_bounds__(THREADS) void dcn_kernel(
    const float* __restrict__ x_l,
    const float* __restrict__ x_0,
    const float* __restrict__ w,
    const float* __restrict__ b,
    float* __restrict__ out)
{
    const int row = blockIdx.x;
    const int t   = threadIdx.x;
    const size_t base4 = (size_t)row * (DIM / 4);

    const float4* __restrict__ xl4 = reinterpret_cast<const float4*>(x_l);
    const float4* __restrict__ x04 = reinterpret_cast<const float4*>(x_0);
    const float4* __restrict__ w4  = reinterpret_cast<const float4*>(w);
    const float4* __restrict__ b4  = reinterpret_cast<const float4*>(b);
    float4* __restrict__ out4      = reinterpret_cast<float4*>(out);

    // Front-batch all loads (default cache ops -- best measured variant).
    float4 a  = xl4[base4 + t];
    float4 c  = x04[base4 + t];
    float4 wv = w4[t];
    float4 bv = b4[t];

    // Partial dot product.
    float local = a.x * wv.x + a.y * wv.y + a.z * wv.z + a.w * wv.w;

    // Warp butterfly reduce.
    #pragma unroll
    for (int off = 16; off > 0; off >>= 1)
        local += __shfl_xor_sync(0xffffffffu, local, off);

    __shared__ float warpsum[THREADS / 32];
    if ((t & 31) == 0) warpsum[t >> 5] = local;
    __syncthreads();

    float s = 0.0f;
    #pragma unroll
    for (int i = 0; i < THREADS / 32; i++) s += warpsum[i];

    // Pure-register epilogue; evict-first store for the write-once stream.
    float4 o;
    o.x = fmaf(c.x, s, bv.x + a.x);
    o.y = fmaf(c.y, s, bv.y + a.y);
    o.z = fmaf(c.z, s, bv.z + a.z);
    o.w = fmaf(c.w, s, bv.w + a.w);
    __stcs(&out4[base4 + t], o);
}

extern "C" void kernel_launch(void* const* d_in, const int* in_sizes, int n_in,
                              void* d_out, int out_size)
{
    const float* x_l = (const float*)d_in[0];
    const float* x_0 = (const float*)d_in[1];
    const float* w   = (const float*)d_in[2];
    const float* b   = (const float*)d_in[3];
    float* out       = (float*)d_out;

    const int B = in_sizes[0] / DIM;  // 65536
    dcn_kernel<<<B, THREADS>>>(x_l, x_0, w, b, out);
}